// round 16
// baseline (speedup 1.0000x reference)
#include <cuda_runtime.h>
#include <cuda_bf16.h>
#include <stdint.h>
#include <math.h>

#define NBt 256
#define POS 676          // 26*26
#define LLt 624
#define DDc 128
#define CHc 256
#define HP  28           // padded grid 28x28
#define NTILE 1352       // NBt*POS/128 (exact)
#define NPSZ ((size_t)NBt*HP*HP*DDc)   // one padded-grid buffer

typedef unsigned long long u64;

// ---- device-global scratch ----
__device__ float          g_Y  [(size_t)NBt*POS*DDc];      // residual stream, fp32
__device__ __nv_bfloat16  g_Ynp[2*NPSZ];                   // LN out, bf16, DOUBLE-BUFFERED
__device__ u64            g_w3F[(size_t)4*9*8*32*32];      // fragment-major conv weights
__device__ __nv_bfloat16  g_w1T[(size_t)4*DDc*CHc];        // [l][d][co]
__device__ int            g_inv[POS];

// ---------------- PTX helpers (baseline PTX only) ----------------
__device__ __forceinline__ uint32_t s2u(const void* p){
  uint32_t a;
  asm("{ .reg .u64 t; cvta.to.shared.u64 t, %1; cvt.u32.u64 %0, t; }" : "=r"(a) : "l"(p));
  return a;
}
#define CP16(dst, src) asm volatile("cp.async.cg.shared.global [%0], [%1], 16;" :: "r"(dst), "l"(src) : "memory")
#define CP_COMMIT()    asm volatile("cp.async.commit_group;" ::: "memory")
#define CP_WAIT(n)     asm volatile("cp.async.wait_group %0;" :: "n"(n) : "memory")

__device__ __forceinline__ void ldsm4(uint32_t addr, uint32_t &r0, uint32_t &r1, uint32_t &r2, uint32_t &r3){
  asm volatile("ldmatrix.sync.aligned.m8n8.x4.shared.b16 {%0,%1,%2,%3}, [%4];"
    : "=r"(r0),"=r"(r1),"=r"(r2),"=r"(r3) : "r"(addr));
}
__device__ __forceinline__ void ldg2(const u64* p, uint32_t &r0, uint32_t &r1){
  asm volatile("ld.global.nc.v2.b32 {%0,%1}, [%2];" : "=r"(r0), "=r"(r1) : "l"(p));
}
__device__ __forceinline__ void mma16816(float* c, uint32_t a0,uint32_t a1,uint32_t a2,uint32_t a3,
                                         uint32_t b0,uint32_t b1){
  asm volatile("mma.sync.aligned.m16n8k16.row.col.f32.bf16.bf16.f32 "
    "{%0,%1,%2,%3}, {%4,%5,%6,%7}, {%8,%9}, {%0,%1,%2,%3};"
    : "+f"(c[0]),"+f"(c[1]),"+f"(c[2]),"+f"(c[3])
    : "r"(a0),"r"(a1),"r"(a2),"r"(a3),"r"(b0),"r"(b1));
}

// ---- packed f32x2 ops ----
__device__ __forceinline__ u64 pk2(float lo, float hi){
  u64 r; asm("mov.b64 %0, {%1, %2};" : "=l"(r) : "f"(lo), "f"(hi)); return r;
}
__device__ __forceinline__ void upk2(u64 v, float &lo, float &hi){
  asm("mov.b64 {%0, %1}, %2;" : "=f"(lo), "=f"(hi) : "l"(v));
}
__device__ __forceinline__ u64 mul2(u64 a, u64 b){
  u64 r; asm("mul.rn.f32x2 %0, %1, %2;" : "=l"(r) : "l"(a), "l"(b)); return r;
}
__device__ __forceinline__ u64 add2(u64 a, u64 b){
  u64 r; asm("add.rn.f32x2 %0, %1, %2;" : "=l"(r) : "l"(a), "l"(b)); return r;
}
__device__ __forceinline__ u64 fma2(u64 a, u64 b, u64 c){
  u64 r; asm("fma.rn.f32x2 %0, %1, %2, %3;" : "=l"(r) : "l"(a), "l"(b), "l"(c)); return r;
}

// branchless MUFU-free packed gelu: 0.5x(1+tanh(x(c0+c1 x^2))), tanh = Pade 7/6
__device__ __forceinline__ u64 gelu2(float v0, float v1){
  const u64 C0  = pk2(0.79788456f, 0.79788456f);
  const u64 C1  = pk2(0.035677408f, 0.035677408f);
  const u64 K378  = pk2(378.f, 378.f);
  const u64 K17325= pk2(17325.f, 17325.f);
  const u64 K135  = pk2(135135.f, 135135.f);
  const u64 K28   = pk2(28.f, 28.f);
  const u64 K3150 = pk2(3150.f, 3150.f);
  const u64 K62370= pk2(62370.f, 62370.f);
  const u64 NONE  = pk2(-1.f, -1.f);
  const u64 HALF  = pk2(0.5f, 0.5f);

  u64 x  = pk2(v0, v1);
  u64 s  = mul2(x, x);
  u64 z  = mul2(x, fma2(C1, s, C0));
  u64 w  = mul2(z, z);
  u64 num = mul2(z, fma2(w, fma2(w, add2(w, K378), K17325), K135));
  u64 den = fma2(w, fma2(w, fma2(w, K28, K3150), K62370), K135);
  float dl, dh; upk2(den, dl, dh);
  float yl = __int_as_float(0x7EF311C3 - __float_as_int(dl));
  float yh = __int_as_float(0x7EF311C3 - __float_as_int(dh));
  u64 y  = pk2(yl, yh);
  u64 nd = mul2(den, NONE);
  y = mul2(y, fma2(nd, y, pk2(2.f,2.f)));
  y = mul2(y, fma2(nd, y, pk2(2.f,2.f)));
  u64 th = mul2(num, y);
  u64 hx = mul2(x, HALF);
  return fma2(th, hx, hx);       // 0.5x + 0.5x*tanh
}

// ---------------- small kernels ----------------
__global__ void k_inv(const int* __restrict__ coords){
  int t = threadIdx.x;
  if (t < POS) g_inv[t] = -1;
  __syncthreads();
  if (t < LLt){
    int r = coords[2*t], c = coords[2*t+1];
    g_inv[r*26 + c] = t;
  }
}

// merged weight prep: blocks [0,1152): w3 fragment pack   [1152,1664): w1T
//                      [1664,8576): g_Ynp border zeroing (BOTH buffers)
__global__ void k_prep(const float* __restrict__ w3, const float* __restrict__ w1){
  int blk = blockIdx.x;
  if (blk < 1152){
    int idx = blk*256 + threadIdx.x;        // [0, 294912)
    int lane = idx & 31;
    int cc   = (idx>>5) & 31;
    int kb   = (idx>>10) & 7;
    int lt   = idx>>13;                     // l*9 + tap, [0,36)
    int n  = cc*8 + (lane>>2);
    int k0 = kb*16 + 2*(lane&3);
    const float* wbase = w3 + (size_t)lt*32768;   // [ci=128][co=256]
    __nv_bfloat162 lo2 = __floats2bfloat162_rn(wbase[(size_t)k0*256 + n],
                                               wbase[(size_t)(k0+1)*256 + n]);
    __nv_bfloat162 hi2 = __floats2bfloat162_rn(wbase[(size_t)(k0+8)*256 + n],
                                               wbase[(size_t)(k0+9)*256 + n]);
    uint32_t u0 = *(uint32_t*)&lo2, u1 = *(uint32_t*)&hi2;
    g_w3F[idx] = ((u64)u1<<32) | (u64)u0;   // v2.b32 load: r0=u0 (b0), r1=u1 (b1)
  } else if (blk < 1664){
    int idx = (blk-1152)*256 + threadIdx.x; // [0, 131072)
    int co = idx & 255;
    int d  = (idx>>8) & 127;
    int l  = idx>>15;
    g_w1T[idx] = __float2bfloat16(w1[((size_t)l*256 + co)*128 + d]);
  } else {
    int idx = (blk-1664)*256 + threadIdx.x; // 256*108*64 entries
    int c2 = idx & 63;
    int j  = (idx >> 6) % 108;
    int b  = (idx >> 6) / 108;
    int r, c;
    if      (j < 28){ r = 0;       c = j; }
    else if (j < 56){ r = 27;      c = j-28; }
    else if (j < 82){ r = j-56+1;  c = 0; }
    else            { r = j-82+1;  c = 27; }
    size_t off = (((size_t)b*HP + r)*HP + c)*DDc + c2*2;
    __nv_bfloat162 z2 = __floats2bfloat162_rn(0.f, 0.f);
    *(__nv_bfloat162*)(g_Ynp + off)        = z2;
    *(__nv_bfloat162*)(g_Ynp + NPSZ + off) = z2;
  }
}

// fused scatter + layer-0 LN (float4 per lane) -> buffer 0
__global__ void k_fill_ln(const float* __restrict__ X, const float* __restrict__ P,
                          const float* __restrict__ scale, const float* __restrict__ bias){
  int cell = blockIdx.x*8 + (threadIdx.x>>5);
  int lane = threadIdx.x & 31;
  int b = cell/POS, sp = cell - b*POS;
  int li = g_inv[sp];
  const float* src = (li >= 0) ? (X + ((size_t)b*LLt + li)*DDc) : P;
  float4 v = ((const float4*)src)[lane];
  ((float4*)(g_Y + (size_t)cell*DDc))[lane] = v;
  float s  = v.x+v.y+v.z+v.w;
  float s2 = v.x*v.x+v.y*v.y+v.z*v.z+v.w*v.w;
  #pragma unroll
  for (int o=16;o;o>>=1){ s += __shfl_xor_sync(~0u,s,o); s2 += __shfl_xor_sync(~0u,s2,o); }
  float mn = s*(1.f/128.f);
  float var = s2*(1.f/128.f) - mn*mn;
  float rs = rsqrtf(var + 1e-5f);
  int h = sp/26, w = sp - h*26;
  __nv_bfloat162* o = (__nv_bfloat162*)(g_Ynp + (((size_t)b*HP + h+1)*HP + (w+1))*DDc);
  float4 sc = ((const float4*)scale)[lane];
  float4 bb = ((const float4*)bias)[lane];
  o[lane*2  ] = __floats2bfloat162_rn((v.x-mn)*rs*sc.x + bb.x, (v.y-mn)*rs*sc.y + bb.y);
  o[lane*2+1] = __floats2bfloat162_rn((v.z-mn)*rs*sc.z + bb.z, (v.w-mn)*rs*sc.w + bb.w);
}

// ---------------- fused conv block: 16 warps; pipelined B-LDG; fused LN / fused gather ----------------
// Reads ynp_in; layers 0-2: RMW g_Y + write next-layer LN into ynp_out.
// Layer 3 (outg != 0): residual-read g_Y, write final token rows directly to out.
__global__ void __launch_bounds__(512,1) k_conv(
    int layer, const float* __restrict__ b3, const float* __restrict__ b1,
    const float* __restrict__ lns, const float* __restrict__ lnb, int do_ln,
    const __nv_bfloat16* __restrict__ ynp_in, __nv_bfloat16* __restrict__ ynp_out,
    float* __restrict__ outg)
{
  extern __shared__ unsigned char smraw[];
  uint32_t sb0 = s2u(smraw);
  uint32_t pad = (0u - sb0) & 1023u;
  unsigned char* smem = smraw + pad;
  const uint32_t sbase = sb0 + pad;

  const int tid = threadIdx.x, lane = tid&31, wid = tid>>5;
  const int wm = wid & 3;          // 4-way M split (32 rows each)
  const int wn = wid >> 2;         // 4-way N split (64 cols each)
  const int lr = lane & 15;
  const int hi = lane >> 4;
  const int sw = lane & 7;

  enum { OFF_TAB=0, OFF_LI=512, OFF_A0=1024, OFF_A1=1024+32768,
         OFF_W=1024+65536 };                         // end = 132096
  // after the 1x1 GEMM, OFF_A0..+64KB is reused as the fp32 Y-row buffer (YS)

  int* baseT = (int*)(smem + OFF_TAB);
  int* liT   = (int*)(smem + OFF_LI);
  if (tid < 128){
    int p = blockIdx.x*128 + tid;
    int b = p/POS, sp = p - b*POS;
    int r = sp/26, c = sp - r*26;
    baseT[tid] = ((b*HP + r)*HP + c)*DDc;     // 3x3 window top-left elem offset
    int li = g_inv[sp];
    liT[tid] = (li >= 0) ? (int)(((size_t)b*LLt + li)*DDc) : -1;
  }
  __syncthreads();

  const u64* w3F = g_w3F + (size_t)layer*9*8192 + wn*256 + lane;
  const __nv_bfloat16* w1T = g_w1T + (size_t)layer*DDc*CHc;

  #define LOAD_A(T_, AOFF) do{                                                  \
    const int tapoff = (((T_)/3)*HP + ((T_)%3))*DDc;                             \
    _Pragma("unroll")                                                            \
    for (int it=0; it<4; it++){                                                  \
      int seg = tid + it*512; int m = seg>>4, c = seg&15;                        \
      const __nv_bfloat16* src = ynp_in + (size_t)(baseT[m] + tapoff) + c*8;     \
      uint32_t dst = sbase + (AOFF) + m*256 + ((c ^ (m&7))<<4);                  \
      CP16(dst, src);                                                            \
    }                                                                            \
  }while(0)

  uint32_t bfr[2][8][2];
  #define LDB(BUF, T_, KB_) do{                                                 \
    const u64* _p = w3F + (size_t)(T_)*8192 + (KB_)*1024;                        \
    _Pragma("unroll")                                                            \
    for (int j=0;j<8;j++) ldg2(_p + j*32, bfr[BUF][j][0], bfr[BUF][j][1]);       \
  }while(0)

  float acc[2][8][4];
  #pragma unroll
  for (int a=0;a<2;a++)
    #pragma unroll
    for (int b=0;b<8;b++)
      #pragma unroll
      for (int q=0;q<4;q++) acc[a][b][q]=0.f;

  LOAD_A(0, OFF_A0); CP_COMMIT();
  LDB(0, 0, 0);

  for (int t=0; t<9; t++){
    if (t>0) __syncthreads();
    if (t<8){
      if ((t+1)&1) LOAD_A(t+1, OFF_A1);
      else         LOAD_A(t+1, OFF_A0);
      CP_COMMIT();
    } else {
      // prefetch w1 tile [128 d][256 co] into OFF_W
      #pragma unroll
      for (int it=0; it<8; it++){
        int seg = tid + it*512; int row = seg>>5, c = seg&31;
        uint32_t dst = sbase + OFF_W + row*512 + ((c ^ (row&7))<<4);
        CP16(dst, w1T + (size_t)row*CHc + c*8);
      }
      CP_COMMIT();
    }
    CP_WAIT(1);
    __syncthreads();

    const uint32_t abuf = sbase + ((t&1)? OFF_A1 : OFF_A0);
    uint32_t Abase[2];
    #pragma unroll
    for (int mb=0;mb<2;mb++) Abase[mb] = abuf + (wm*32 + mb*16 + lr)*256;

    #pragma unroll
    for (int kb=0; kb<8; kb++){
      const int cur = kb&1;
      if (kb<7)      LDB(cur^1, t,   kb+1);
      else if (t<8)  LDB(cur^1, t+1, 0);

      const uint32_t off = (uint32_t)(((2*kb + hi) ^ sw) << 4);
      uint32_t a[2][4];
      #pragma unroll
      for (int mb=0;mb<2;mb++) ldsm4(Abase[mb]+off, a[mb][0],a[mb][1],a[mb][2],a[mb][3]);
      #pragma unroll
      for (int mb=0;mb<2;mb++){
        #pragma unroll
        for (int nb2=0;nb2<4;nb2++){
          mma16816(acc[mb][2*nb2  ], a[mb][0],a[mb][1],a[mb][2],a[mb][3], bfr[cur][2*nb2  ][0], bfr[cur][2*nb2  ][1]);
          mma16816(acc[mb][2*nb2+1], a[mb][0],a[mb][1],a[mb][2],a[mb][3], bfr[cur][2*nb2+1][0], bfr[cur][2*nb2+1][1]);
        }
      }
    }
  }
  __syncthreads();

  // ---- epilogue 1: bias + packed fast gelu -> bf16 G [128 m][256 k] at OFF_A0 ----
  {
    const int rq = lane>>2;
    #pragma unroll
    for (int mb=0;mb<2;mb++){
      const int r0 = wm*32 + mb*16 + rq;
      const int r1 = r0 + 8;
      #pragma unroll
      for (int nb=0;nb<8;nb++){
        const int col = wn*64 + nb*8 + 2*(lane&3);
        float2 bv = *(const float2*)(b3 + col);
        u64 g0 = gelu2(acc[mb][nb][0] + bv.x, acc[mb][nb][1] + bv.y);
        u64 g1 = gelu2(acc[mb][nb][2] + bv.x, acc[mb][nb][3] + bv.y);
        float v0, v1, v2, v3;
        upk2(g0, v0, v1);
        upk2(g1, v2, v3);
        const int chunk = col>>3, wb = (col&7)*2;
        uint32_t o0 = (uint32_t)(r0*512 + ((chunk ^ (r0&7))<<4) + wb);
        uint32_t o1 = (uint32_t)(r1*512 + ((chunk ^ (r1&7))<<4) + wb);
        __nv_bfloat162 h0 = __floats2bfloat162_rn(v0, v1);
        __nv_bfloat162 h1 = __floats2bfloat162_rn(v2, v3);
        *(uint32_t*)(smem + OFF_A0 + o0) = *(uint32_t*)&h0;
        *(uint32_t*)(smem + OFF_A0 + o1) = *(uint32_t*)&h1;
      }
    }
  }
  CP_WAIT(0);                            // w1 tile resident
  __syncthreads();                       // G visible to all warps

  // ---- 1x1 GEMM: D2[128,128] = G[128,256] @ w1T^T (warp tile 32x32) ----
  float a2[2][4][4];
  #pragma unroll
  for (int a=0;a<2;a++)
    #pragma unroll
    for (int b=0;b<4;b++)
      #pragma unroll
      for (int q=0;q<4;q++) a2[a][b][q]=0.f;
  {
    uint32_t Gbase[2], Wbase[2];
    #pragma unroll
    for (int mb=0;mb<2;mb++) Gbase[mb] = sbase + OFF_A0 + (wm*32 + mb*16 + lr)*512;
    #pragma unroll
    for (int nb2=0;nb2<2;nb2++) Wbase[nb2] = sbase + OFF_W + (wn*32 + nb2*16 + lr)*512;

    #pragma unroll
    for (int kb=0; kb<16; kb++){
      const uint32_t off = (uint32_t)(((2*kb + hi) ^ sw) << 4);
      uint32_t a[2][4], bf[2][4];
      #pragma unroll
      for (int mb=0;mb<2;mb++) ldsm4(Gbase[mb]+off, a[mb][0],a[mb][1],a[mb][2],a[mb][3]);
      #pragma unroll
      for (int nb2=0;nb2<2;nb2++) ldsm4(Wbase[nb2]+off, bf[nb2][0],bf[nb2][1],bf[nb2][2],bf[nb2][3]);
      #pragma unroll
      for (int mb=0;mb<2;mb++){
        #pragma unroll
        for (int nb2=0;nb2<2;nb2++){
          mma16816(a2[mb][2*nb2  ], a[mb][0],a[mb][1],a[mb][2],a[mb][3], bf[nb2][0], bf[nb2][2]);
          mma16816(a2[mb][2*nb2+1], a[mb][0],a[mb][1],a[mb][2],a[mb][3], bf[nb2][1], bf[nb2][3]);
        }
      }
    }
  }
  if (do_ln) __syncthreads();            // all warps done reading G before YS overwrite

  // ---- epilogue 2: bias + residual; write g_Y (+YS) or final out rows ----
  {
    const int rq = lane>>2;
    #pragma unroll
    for (int mb=0;mb<2;mb++){
      const int r0 = wm*32 + mb*16 + rq;
      const int r1 = r0 + 8;
      const float* y0 = g_Y + ((size_t)blockIdx.x*128 + r0)*DDc;
      float* w0;
      float* w1p;
      if (outg){
        int ob0 = liT[r0], ob1 = liT[r1];
        w0  = (ob0 >= 0) ? (outg + ob0) : 0;
        w1p = (ob1 >= 0) ? (outg + ob1) : 0;
      } else {
        w0  = (float*)y0;
        w1p = (float*)(y0 + 8*DDc);
      }
      #pragma unroll
      for (int nb=0;nb<4;nb++){
        const int d = wn*32 + nb*8 + 2*(lane&3);
        float2 bv = *(const float2*)(b1 + d);
        float2 ya = *(const float2*)(y0 + d);
        ya.x += a2[mb][nb][0] + bv.x;
        ya.y += a2[mb][nb][1] + bv.y;
        if (w0) *(float2*)(w0 + d) = ya;
        float2 yb = *(const float2*)(y0 + 8*DDc + d);
        yb.x += a2[mb][nb][2] + bv.x;
        yb.y += a2[mb][nb][3] + bv.y;
        if (w1p) *(float2*)(w1p + d) = yb;
        if (do_ln){
          const uint32_t ch = (uint32_t)(d>>3);
          const uint32_t ob = (uint32_t)((d&7)*4);
          *(float2*)(smem + OFF_A0 + r0*512 + ((ch ^ (uint32_t)(r0&7))<<5) + ob) = ya;
          *(float2*)(smem + OFF_A0 + r1*512 + ((ch ^ (uint32_t)(r1&7))<<5) + ob) = yb;
        }
      }
    }
  }

  // ---- epilogue 3: fused next-layer LN, warp-per-row, coalesced writes -> ynp_out ----
  if (do_ln){
    __syncthreads();
    float4 sc = ((const float4*)lns)[lane];
    float4 bb = ((const float4*)lnb)[lane];
    #pragma unroll
    for (int rr=0; rr<8; rr++){
      const int row = wid*8 + rr;
      float4 v = *(float4*)(smem + OFF_A0 + row*512 +
                            (((uint32_t)(lane>>1) ^ (uint32_t)(row&7))<<5) + (lane&1)*16);
      float s  = v.x+v.y+v.z+v.w;
      float s2 = v.x*v.x+v.y*v.y+v.z*v.z+v.w*v.w;
      #pragma unroll
      for (int o=16;o;o>>=1){ s += __shfl_xor_sync(~0u,s,o); s2 += __shfl_xor_sync(~0u,s2,o); }
      float mn = s*(1.f/128.f);
      float var = s2*(1.f/128.f) - mn*mn;
      float rs = rsqrtf(var + 1e-5f);
      __nv_bfloat162* o2 = (__nv_bfloat162*)(ynp_out + (size_t)baseT[row] + 29*DDc);
      o2[lane*2  ] = __floats2bfloat162_rn((v.x-mn)*rs*sc.x + bb.x, (v.y-mn)*rs*sc.y + bb.y);
      o2[lane*2+1] = __floats2bfloat162_rn((v.z-mn)*rs*sc.z + bb.z, (v.w-mn)*rs*sc.w + bb.w);
    }
  }
  #undef LOAD_A
  #undef LDB
}

// ---------------- launch ----------------
extern "C" void kernel_launch(void* const* d_in, const int* in_sizes, int n_in,
                              void* d_out, int out_size){
  const float* X        = (const float*)d_in[0];
  const int*   coords   = (const int*)  d_in[1];
  const float* P        = (const float*)d_in[2];
  const float* ln_scale = (const float*)d_in[3];
  const float* ln_bias  = (const float*)d_in[4];
  const float* w3       = (const float*)d_in[5];
  const float* b3       = (const float*)d_in[6];
  const float* w1       = (const float*)d_in[7];
  const float* b1       = (const float*)d_in[8];
  float* out = (float*)d_out;

  const int SMEM_SZ = 132096 + 1024;
  cudaFuncSetAttribute(k_conv, cudaFuncAttributeMaxDynamicSharedMemorySize, SMEM_SZ);

  __nv_bfloat16* ynp = 0; cudaGetSymbolAddress((void**)&ynp, g_Ynp);

  // launch order keeps index 3 (ncu's sample slot) = k_conv layer 0
  k_inv    <<<1, 1024>>>(coords);                                   // 0
  k_prep   <<<8576, 256>>>(w3, w1);                                 // 1
  k_fill_ln<<<21632, 256>>>(X, P, ln_scale, ln_bias);               // 2 -> buf 0
  for (int l=0; l<4; l++){
    int nl = (l<3) ? (l+1) : 3;
    const __nv_bfloat16* in  = ynp + (size_t)(l&1)*NPSZ;
    __nv_bfloat16*       outp= ynp + (size_t)((l+1)&1)*NPSZ;
    k_conv<<<NTILE, 512, SMEM_SZ>>>(l, b3 + l*CHc, b1 + l*DDc,
                                    ln_scale + nl*DDc, ln_bias + nl*DDc,
                                    (l<3)?1:0, in, outp,
                                    (l==3)? out : (float*)0);
  }
  // final layer writes token rows directly to out — no gather kernel
}

// round 17
// speedup vs baseline: 1.0583x; 1.0583x over previous
#include <cuda_runtime.h>
#include <cuda_bf16.h>
#include <stdint.h>
#include <math.h>

#define NBt 256
#define POS 676          // 26*26
#define LLt 624
#define DDc 128
#define CHc 256
#define HP  28           // padded grid 28x28
#define NTILE 1352       // NBt*POS/128 (exact)
#define NPSZ ((size_t)NBt*HP*HP*DDc)   // one padded-grid buffer

typedef unsigned long long u64;

// ---- device-global scratch ----
__device__ float          g_Y  [(size_t)NBt*POS*DDc];      // residual stream, fp32
__device__ __nv_bfloat16  g_Ynp[2*NPSZ];                   // LN out, bf16, DOUBLE-BUFFERED
__device__ u64            g_w3F[(size_t)4*9*8*32*32];      // fragment-major conv weights
__device__ __nv_bfloat16  g_w1T[(size_t)4*DDc*CHc];        // [l][d][co]
__device__ int            g_inv[POS];

// ---------------- PTX helpers (baseline PTX only) ----------------
__device__ __forceinline__ uint32_t s2u(const void* p){
  uint32_t a;
  asm("{ .reg .u64 t; cvta.to.shared.u64 t, %1; cvt.u32.u64 %0, t; }" : "=r"(a) : "l"(p));
  return a;
}
#define CP16(dst, src) asm volatile("cp.async.cg.shared.global [%0], [%1], 16;" :: "r"(dst), "l"(src) : "memory")
#define CP_COMMIT()    asm volatile("cp.async.commit_group;" ::: "memory")
#define CP_WAIT(n)     asm volatile("cp.async.wait_group %0;" :: "n"(n) : "memory")

__device__ __forceinline__ void ldsm4(uint32_t addr, uint32_t &r0, uint32_t &r1, uint32_t &r2, uint32_t &r3){
  asm volatile("ldmatrix.sync.aligned.m8n8.x4.shared.b16 {%0,%1,%2,%3}, [%4];"
    : "=r"(r0),"=r"(r1),"=r"(r2),"=r"(r3) : "r"(addr));
}
__device__ __forceinline__ void ldg2(const u64* p, uint32_t &r0, uint32_t &r1){
  asm volatile("ld.global.nc.v2.b32 {%0,%1}, [%2];" : "=r"(r0), "=r"(r1) : "l"(p));
}
__device__ __forceinline__ void mma16816(float* c, uint32_t a0,uint32_t a1,uint32_t a2,uint32_t a3,
                                         uint32_t b0,uint32_t b1){
  asm volatile("mma.sync.aligned.m16n8k16.row.col.f32.bf16.bf16.f32 "
    "{%0,%1,%2,%3}, {%4,%5,%6,%7}, {%8,%9}, {%0,%1,%2,%3};"
    : "+f"(c[0]),"+f"(c[1]),"+f"(c[2]),"+f"(c[3])
    : "r"(a0),"r"(a1),"r"(a2),"r"(a3),"r"(b0),"r"(b1));
}

// ---- packed f32x2 ops ----
__device__ __forceinline__ u64 pk2(float lo, float hi){
  u64 r; asm("mov.b64 %0, {%1, %2};" : "=l"(r) : "f"(lo), "f"(hi)); return r;
}
__device__ __forceinline__ void upk2(u64 v, float &lo, float &hi){
  asm("mov.b64 {%0, %1}, %2;" : "=f"(lo), "=f"(hi) : "l"(v));
}
__device__ __forceinline__ u64 mul2(u64 a, u64 b){
  u64 r; asm("mul.rn.f32x2 %0, %1, %2;" : "=l"(r) : "l"(a), "l"(b)); return r;
}
__device__ __forceinline__ u64 add2(u64 a, u64 b){
  u64 r; asm("add.rn.f32x2 %0, %1, %2;" : "=l"(r) : "l"(a), "l"(b)); return r;
}
__device__ __forceinline__ u64 fma2(u64 a, u64 b, u64 c){
  u64 r; asm("fma.rn.f32x2 %0, %1, %2, %3;" : "=l"(r) : "l"(a), "l"(b), "l"(c)); return r;
}

// branchless MUFU-free packed gelu: 0.5x(1+tanh(x(c0+c1 x^2))), tanh = Pade 7/6
__device__ __forceinline__ u64 gelu2(float v0, float v1){
  const u64 C0  = pk2(0.79788456f, 0.79788456f);
  const u64 C1  = pk2(0.035677408f, 0.035677408f);
  const u64 K378  = pk2(378.f, 378.f);
  const u64 K17325= pk2(17325.f, 17325.f);
  const u64 K135  = pk2(135135.f, 135135.f);
  const u64 K28   = pk2(28.f, 28.f);
  const u64 K3150 = pk2(3150.f, 3150.f);
  const u64 K62370= pk2(62370.f, 62370.f);
  const u64 NONE  = pk2(-1.f, -1.f);
  const u64 HALF  = pk2(0.5f, 0.5f);

  u64 x  = pk2(v0, v1);
  u64 s  = mul2(x, x);
  u64 z  = mul2(x, fma2(C1, s, C0));
  u64 w  = mul2(z, z);
  u64 num = mul2(z, fma2(w, fma2(w, add2(w, K378), K17325), K135));
  u64 den = fma2(w, fma2(w, fma2(w, K28, K3150), K62370), K135);
  float dl, dh; upk2(den, dl, dh);
  float yl = __int_as_float(0x7EF311C3 - __float_as_int(dl));
  float yh = __int_as_float(0x7EF311C3 - __float_as_int(dh));
  u64 y  = pk2(yl, yh);
  u64 nd = mul2(den, NONE);
  y = mul2(y, fma2(nd, y, pk2(2.f,2.f)));
  y = mul2(y, fma2(nd, y, pk2(2.f,2.f)));
  u64 th = mul2(num, y);
  u64 hx = mul2(x, HALF);
  return fma2(th, hx, hx);       // 0.5x + 0.5x*tanh
}

// ---------------- small kernels ----------------
__global__ void k_inv(const int* __restrict__ coords){
  int t = threadIdx.x;
  if (t < POS) g_inv[t] = -1;
  __syncthreads();
  if (t < LLt){
    int r = coords[2*t], c = coords[2*t+1];
    g_inv[r*26 + c] = t;
  }
}

// merged weight prep: blocks [0,1152): w3 fragment pack   [1152,1664): w1T
//                      [1664,8576): g_Ynp border zeroing (BOTH buffers)
__global__ void k_prep(const float* __restrict__ w3, const float* __restrict__ w1){
  int blk = blockIdx.x;
  if (blk < 1152){
    int idx = blk*256 + threadIdx.x;        // [0, 294912)
    int lane = idx & 31;
    int cc   = (idx>>5) & 31;
    int kb   = (idx>>10) & 7;
    int lt   = idx>>13;                     // l*9 + tap, [0,36)
    int n  = cc*8 + (lane>>2);
    int k0 = kb*16 + 2*(lane&3);
    const float* wbase = w3 + (size_t)lt*32768;   // [ci=128][co=256]
    __nv_bfloat162 lo2 = __floats2bfloat162_rn(wbase[(size_t)k0*256 + n],
                                               wbase[(size_t)(k0+1)*256 + n]);
    __nv_bfloat162 hi2 = __floats2bfloat162_rn(wbase[(size_t)(k0+8)*256 + n],
                                               wbase[(size_t)(k0+9)*256 + n]);
    uint32_t u0 = *(uint32_t*)&lo2, u1 = *(uint32_t*)&hi2;
    g_w3F[idx] = ((u64)u1<<32) | (u64)u0;   // v2.b32 load: r0=u0 (b0), r1=u1 (b1)
  } else if (blk < 1664){
    int idx = (blk-1152)*256 + threadIdx.x; // [0, 131072)
    int co = idx & 255;
    int d  = (idx>>8) & 127;
    int l  = idx>>15;
    g_w1T[idx] = __float2bfloat16(w1[((size_t)l*256 + co)*128 + d]);
  } else {
    int idx = (blk-1664)*256 + threadIdx.x; // 256*108*64 entries
    int c2 = idx & 63;
    int j  = (idx >> 6) % 108;
    int b  = (idx >> 6) / 108;
    int r, c;
    if      (j < 28){ r = 0;       c = j; }
    else if (j < 56){ r = 27;      c = j-28; }
    else if (j < 82){ r = j-56+1;  c = 0; }
    else            { r = j-82+1;  c = 27; }
    size_t off = (((size_t)b*HP + r)*HP + c)*DDc + c2*2;
    __nv_bfloat162 z2 = __floats2bfloat162_rn(0.f, 0.f);
    *(__nv_bfloat162*)(g_Ynp + off)        = z2;
    *(__nv_bfloat162*)(g_Ynp + NPSZ + off) = z2;
  }
}

// fused scatter + layer-0 LN (float4 per lane) -> buffer 0
__global__ void k_fill_ln(const float* __restrict__ X, const float* __restrict__ P,
                          const float* __restrict__ scale, const float* __restrict__ bias){
  int cell = blockIdx.x*8 + (threadIdx.x>>5);
  int lane = threadIdx.x & 31;
  int b = cell/POS, sp = cell - b*POS;
  int li = g_inv[sp];
  const float* src = (li >= 0) ? (X + ((size_t)b*LLt + li)*DDc) : P;
  float4 v = ((const float4*)src)[lane];
  ((float4*)(g_Y + (size_t)cell*DDc))[lane] = v;
  float s  = v.x+v.y+v.z+v.w;
  float s2 = v.x*v.x+v.y*v.y+v.z*v.z+v.w*v.w;
  #pragma unroll
  for (int o=16;o;o>>=1){ s += __shfl_xor_sync(~0u,s,o); s2 += __shfl_xor_sync(~0u,s2,o); }
  float mn = s*(1.f/128.f);
  float var = s2*(1.f/128.f) - mn*mn;
  float rs = rsqrtf(var + 1e-5f);
  int h = sp/26, w = sp - h*26;
  __nv_bfloat162* o = (__nv_bfloat162*)(g_Ynp + (((size_t)b*HP + h+1)*HP + (w+1))*DDc);
  float4 sc = ((const float4*)scale)[lane];
  float4 bb = ((const float4*)bias)[lane];
  o[lane*2  ] = __floats2bfloat162_rn((v.x-mn)*rs*sc.x + bb.x, (v.y-mn)*rs*sc.y + bb.y);
  o[lane*2+1] = __floats2bfloat162_rn((v.z-mn)*rs*sc.z + bb.z, (v.w-mn)*rs*sc.w + bb.w);
}

// float4 per thread gather (grid must be NBt*LLt*DDc/4/256 = 19968 blocks)
__global__ void k_gather(const int* __restrict__ coords, float* __restrict__ out){
  unsigned idx = blockIdx.x*256u + threadIdx.x;   // 4 floats per thread
  int c4 = idx & 31;
  int l = (idx >> 5) % LLt;
  int b = (idx >> 5) / LLt;
  int r = coords[2*l], cc = coords[2*l+1];
  float4 v = ((const float4*)(g_Y + ((size_t)b*POS + r*26 + cc)*DDc))[c4];
  ((float4*)out)[(size_t)idx] = v;
}

// ---------------- fused conv block: 16 warps; pipelined B-LDG; fused next-layer LN ----------------
// Reads ynp_in (this layer's LN grid), writes ynp_out (next layer's) — ping-pong, race-free.
// DO_LN is compile-time: layer 3 gets a stripped epilogue.
template<int DO_LN>
__global__ void __launch_bounds__(512,1) k_conv(
    int layer, const float* __restrict__ b3, const float* __restrict__ b1,
    const float* __restrict__ lns, const float* __restrict__ lnb,
    const __nv_bfloat16* __restrict__ ynp_in, __nv_bfloat16* __restrict__ ynp_out)
{
  extern __shared__ unsigned char smraw[];
  uint32_t sb0 = s2u(smraw);
  uint32_t pad = (0u - sb0) & 1023u;
  unsigned char* smem = smraw + pad;
  const uint32_t sbase = sb0 + pad;

  const int tid = threadIdx.x, lane = tid&31, wid = tid>>5;
  const int wm = wid & 3;          // 4-way M split (32 rows each)
  const int wn = wid >> 2;         // 4-way N split (64 cols each)
  const int lr = lane & 15;
  const int hi = lane >> 4;
  const int sw = lane & 7;

  enum { OFF_TAB=0, OFF_A0=1024, OFF_A1=1024+32768,
         OFF_W=1024+65536 };                         // end = 132096
  // after the 1x1 GEMM, OFF_A0..+64KB is reused as the fp32 Y-row buffer (YS)

  int* baseT = (int*)(smem + OFF_TAB);
  if (tid < 128){
    int p = blockIdx.x*128 + tid;
    int b = p/POS, sp = p - b*POS;
    int r = sp/26, c = sp - r*26;
    baseT[tid] = ((b*HP + r)*HP + c)*DDc;     // 3x3 window top-left elem offset
  }
  __syncthreads();

  const u64* w3F = g_w3F + (size_t)layer*9*8192 + wn*256 + lane;
  const __nv_bfloat16* w1T = g_w1T + (size_t)layer*DDc*CHc;

  #define LOAD_A(T_, AOFF) do{                                                  \
    const int tapoff = (((T_)/3)*HP + ((T_)%3))*DDc;                             \
    _Pragma("unroll")                                                            \
    for (int it=0; it<4; it++){                                                  \
      int seg = tid + it*512; int m = seg>>4, c = seg&15;                        \
      const __nv_bfloat16* src = ynp_in + (size_t)(baseT[m] + tapoff) + c*8;     \
      uint32_t dst = sbase + (AOFF) + m*256 + ((c ^ (m&7))<<4);                  \
      CP16(dst, src);                                                            \
    }                                                                            \
  }while(0)

  uint32_t bfr[2][8][2];
  #define LDB(BUF, T_, KB_) do{                                                 \
    const u64* _p = w3F + (size_t)(T_)*8192 + (KB_)*1024;                        \
    _Pragma("unroll")                                                            \
    for (int j=0;j<8;j++) ldg2(_p + j*32, bfr[BUF][j][0], bfr[BUF][j][1]);       \
  }while(0)

  float acc[2][8][4];
  #pragma unroll
  for (int a=0;a<2;a++)
    #pragma unroll
    for (int b=0;b<8;b++)
      #pragma unroll
      for (int q=0;q<4;q++) acc[a][b][q]=0.f;

  LOAD_A(0, OFF_A0); CP_COMMIT();
  LDB(0, 0, 0);

  for (int t=0; t<9; t++){
    if (t>0) __syncthreads();
    if (t<8){
      if ((t+1)&1) LOAD_A(t+1, OFF_A1);
      else         LOAD_A(t+1, OFF_A0);
      CP_COMMIT();
    } else {
      // prefetch w1 tile [128 d][256 co] into OFF_W
      #pragma unroll
      for (int it=0; it<8; it++){
        int seg = tid + it*512; int row = seg>>5, c = seg&31;
        uint32_t dst = sbase + OFF_W + row*512 + ((c ^ (row&7))<<4);
        CP16(dst, w1T + (size_t)row*CHc + c*8);
      }
      CP_COMMIT();
    }
    CP_WAIT(1);
    __syncthreads();

    const uint32_t abuf = sbase + ((t&1)? OFF_A1 : OFF_A0);
    uint32_t Abase[2];
    #pragma unroll
    for (int mb=0;mb<2;mb++) Abase[mb] = abuf + (wm*32 + mb*16 + lr)*256;

    #pragma unroll
    for (int kb=0; kb<8; kb++){
      const int cur = kb&1;
      if (kb<7)      LDB(cur^1, t,   kb+1);
      else if (t<8)  LDB(cur^1, t+1, 0);

      const uint32_t off = (uint32_t)(((2*kb + hi) ^ sw) << 4);
      uint32_t a[2][4];
      #pragma unroll
      for (int mb=0;mb<2;mb++) ldsm4(Abase[mb]+off, a[mb][0],a[mb][1],a[mb][2],a[mb][3]);
      #pragma unroll
      for (int mb=0;mb<2;mb++){
        #pragma unroll
        for (int nb2=0;nb2<4;nb2++){
          mma16816(acc[mb][2*nb2  ], a[mb][0],a[mb][1],a[mb][2],a[mb][3], bfr[cur][2*nb2  ][0], bfr[cur][2*nb2  ][1]);
          mma16816(acc[mb][2*nb2+1], a[mb][0],a[mb][1],a[mb][2],a[mb][3], bfr[cur][2*nb2+1][0], bfr[cur][2*nb2+1][1]);
        }
      }
    }
  }
  __syncthreads();

  // ---- epilogue 1: bias + packed fast gelu -> bf16 G [128 m][256 k] at OFF_A0 ----
  {
    const int rq = lane>>2;
    #pragma unroll
    for (int mb=0;mb<2;mb++){
      const int r0 = wm*32 + mb*16 + rq;
      const int r1 = r0 + 8;
      #pragma unroll
      for (int nb=0;nb<8;nb++){
        const int col = wn*64 + nb*8 + 2*(lane&3);
        float2 bv = *(const float2*)(b3 + col);
        u64 g0 = gelu2(acc[mb][nb][0] + bv.x, acc[mb][nb][1] + bv.y);
        u64 g1 = gelu2(acc[mb][nb][2] + bv.x, acc[mb][nb][3] + bv.y);
        float v0, v1, v2, v3;
        upk2(g0, v0, v1);
        upk2(g1, v2, v3);
        const int chunk = col>>3, wb = (col&7)*2;
        uint32_t o0 = (uint32_t)(r0*512 + ((chunk ^ (r0&7))<<4) + wb);
        uint32_t o1 = (uint32_t)(r1*512 + ((chunk ^ (r1&7))<<4) + wb);
        __nv_bfloat162 h0 = __floats2bfloat162_rn(v0, v1);
        __nv_bfloat162 h1 = __floats2bfloat162_rn(v2, v3);
        *(uint32_t*)(smem + OFF_A0 + o0) = *(uint32_t*)&h0;
        *(uint32_t*)(smem + OFF_A0 + o1) = *(uint32_t*)&h1;
      }
    }
  }
  CP_WAIT(0);                            // w1 tile resident
  __syncthreads();                       // G visible to all warps

  // ---- 1x1 GEMM: D2[128,128] = G[128,256] @ w1T^T (warp tile 32x32) ----
  float a2[2][4][4];
  #pragma unroll
  for (int a=0;a<2;a++)
    #pragma unroll
    for (int b=0;b<4;b++)
      #pragma unroll
      for (int q=0;q<4;q++) a2[a][b][q]=0.f;
  {
    uint32_t Gbase[2], Wbase[2];
    #pragma unroll
    for (int mb=0;mb<2;mb++) Gbase[mb] = sbase + OFF_A0 + (wm*32 + mb*16 + lr)*512;
    #pragma unroll
    for (int nb2=0;nb2<2;nb2++) Wbase[nb2] = sbase + OFF_W + (wn*32 + nb2*16 + lr)*512;

    #pragma unroll
    for (int kb=0; kb<16; kb++){
      const uint32_t off = (uint32_t)(((2*kb + hi) ^ sw) << 4);
      uint32_t a[2][4], bf[2][4];
      #pragma unroll
      for (int mb=0;mb<2;mb++) ldsm4(Gbase[mb]+off, a[mb][0],a[mb][1],a[mb][2],a[mb][3]);
      #pragma unroll
      for (int nb2=0;nb2<2;nb2++) ldsm4(Wbase[nb2]+off, bf[nb2][0],bf[nb2][1],bf[nb2][2],bf[nb2][3]);
      #pragma unroll
      for (int mb=0;mb<2;mb++){
        #pragma unroll
        for (int nb2=0;nb2<2;nb2++){
          mma16816(a2[mb][2*nb2  ], a[mb][0],a[mb][1],a[mb][2],a[mb][3], bf[nb2][0], bf[nb2][2]);
          mma16816(a2[mb][2*nb2+1], a[mb][0],a[mb][1],a[mb][2],a[mb][3], bf[nb2][1], bf[nb2][3]);
        }
      }
    }
  }
  if (DO_LN) __syncthreads();            // all warps done reading G before YS overwrite

  // ---- epilogue 2: bias + residual RMW into g_Y (+ stage rows into smem YS) ----
  {
    const int rq = lane>>2;
    #pragma unroll
    for (int mb=0;mb<2;mb++){
      const int r0 = wm*32 + mb*16 + rq;
      float* y0 = g_Y + ((size_t)blockIdx.x*128 + r0)*DDc;
      #pragma unroll
      for (int nb=0;nb<4;nb++){
        const int d = wn*32 + nb*8 + 2*(lane&3);
        float2 bv = *(const float2*)(b1 + d);
        float2 ya = *(float2*)(y0 + d);
        ya.x += a2[mb][nb][0] + bv.x;
        ya.y += a2[mb][nb][1] + bv.y;
        *(float2*)(y0 + d) = ya;
        float2 yb = *(float2*)(y0 + 8*DDc + d);
        yb.x += a2[mb][nb][2] + bv.x;
        yb.y += a2[mb][nb][3] + bv.y;
        *(float2*)(y0 + 8*DDc + d) = yb;
        if (DO_LN){
          const int r1 = r0 + 8;
          const uint32_t ch = (uint32_t)(d>>3);
          const uint32_t ob = (uint32_t)((d&7)*4);
          *(float2*)(smem + OFF_A0 + r0*512 + ((ch ^ (uint32_t)(r0&7))<<5) + ob) = ya;
          *(float2*)(smem + OFF_A0 + r1*512 + ((ch ^ (uint32_t)(r1&7))<<5) + ob) = yb;
        }
      }
    }
  }

  // ---- epilogue 3: fused next-layer LN, warp-per-row, coalesced writes -> ynp_out ----
  if (DO_LN){
    __syncthreads();
    float4 sc = ((const float4*)lns)[lane];
    float4 bb = ((const float4*)lnb)[lane];
    #pragma unroll
    for (int rr=0; rr<8; rr++){
      const int row = wid*8 + rr;
      float4 v = *(float4*)(smem + OFF_A0 + row*512 +
                            (((uint32_t)(lane>>1) ^ (uint32_t)(row&7))<<5) + (lane&1)*16);
      float s  = v.x+v.y+v.z+v.w;
      float s2 = v.x*v.x+v.y*v.y+v.z*v.z+v.w*v.w;
      #pragma unroll
      for (int o=16;o;o>>=1){ s += __shfl_xor_sync(~0u,s,o); s2 += __shfl_xor_sync(~0u,s2,o); }
      float mn = s*(1.f/128.f);
      float var = s2*(1.f/128.f) - mn*mn;
      float rs = rsqrtf(var + 1e-5f);
      __nv_bfloat162* o2 = (__nv_bfloat162*)(ynp_out + (size_t)baseT[row] + 29*DDc);
      o2[lane*2  ] = __floats2bfloat162_rn((v.x-mn)*rs*sc.x + bb.x, (v.y-mn)*rs*sc.y + bb.y);
      o2[lane*2+1] = __floats2bfloat162_rn((v.z-mn)*rs*sc.z + bb.z, (v.w-mn)*rs*sc.w + bb.w);
    }
  }
  #undef LOAD_A
  #undef LDB
}

// ---------------- launch ----------------
extern "C" void kernel_launch(void* const* d_in, const int* in_sizes, int n_in,
                              void* d_out, int out_size){
  const float* X        = (const float*)d_in[0];
  const int*   coords   = (const int*)  d_in[1];
  const float* P        = (const float*)d_in[2];
  const float* ln_scale = (const float*)d_in[3];
  const float* ln_bias  = (const float*)d_in[4];
  const float* w3       = (const float*)d_in[5];
  const float* b3       = (const float*)d_in[6];
  const float* w1       = (const float*)d_in[7];
  const float* b1       = (const float*)d_in[8];
  float* out = (float*)d_out;

  const int SMEM_SZ = 132096 + 1024;
  cudaFuncSetAttribute(k_conv<1>, cudaFuncAttributeMaxDynamicSharedMemorySize, SMEM_SZ);
  cudaFuncSetAttribute(k_conv<0>, cudaFuncAttributeMaxDynamicSharedMemorySize, SMEM_SZ);

  __nv_bfloat16* ynp = 0; cudaGetSymbolAddress((void**)&ynp, g_Ynp);

  // launch order keeps index 3 (ncu's sample slot) = k_conv layer 0
  k_inv    <<<1, 1024>>>(coords);                                   // 0
  k_prep   <<<8576, 256>>>(w3, w1);                                 // 1
  k_fill_ln<<<21632, 256>>>(X, P, ln_scale, ln_bias);               // 2 -> buf 0
  for (int l=0; l<3; l++){
    int nl = l+1;
    const __nv_bfloat16* in  = ynp + (size_t)(l&1)*NPSZ;
    __nv_bfloat16*       outp= ynp + (size_t)((l+1)&1)*NPSZ;
    k_conv<1><<<NTILE, 512, SMEM_SZ>>>(l, b3 + l*CHc, b1 + l*DDc,
                                       ln_scale + nl*DDc, ln_bias + nl*DDc,
                                       in, outp);
  }
  k_conv<0><<<NTILE, 512, SMEM_SZ>>>(3, b3 + 3*CHc, b1 + 3*DDc,
                                     ln_scale + 3*DDc, ln_bias + 3*DDc,
                                     ynp + NPSZ, ynp);
  k_gather<<<19968, 256>>>(coords, out);   // 20,447,232 floats / 4 / 256
}